// round 4
// baseline (speedup 1.0000x reference)
#include <cuda_runtime.h>
#include <cuda_bf16.h>
#include <math.h>

// Problem constants (match reference_code)
#define NN 50000
#define EE 400000
#define BB 50

// ---------------- scratch (static device allocations: allowed) ----------------
__device__ __align__(16) float g_bufA[(size_t)NN * 512];
__device__ __align__(16) float g_bufB[(size_t)NN * 512];
__device__ __align__(16) float g_deg[NN];     // degree, then overwritten with dinv
__device__ __align__(16) float g_self[NN];    // dinv*dinv
__device__ __align__(16) float g_enorm[EE];   // dinv[src]*dinv[dst]
__device__ int g_is64;                        // index dtype flag (1 = int64, 0 = int32)

__device__ __forceinline__ float* selbuf(int w) { return (w == 0) ? g_bufA : g_bufB; }

// Index accessor: element i of an index array that is either int32 or int64.
__device__ __forceinline__ int ld_idx(const void* p, long long i) {
    if (g_is64) return (int)((const long long*)p)[i];
    return ((const int*)p)[i];
}

// ---------------- dtype detection ----------------
// If the buffer is int64 (values in [0, 50000) << 2^31), every odd int32 word
// is zero. For int32 random indices that's essentially impossible over 2048 lanes.
__global__ void detect_kernel(const int* __restrict__ ei32) {
    if (threadIdx.x == 0 && blockIdx.x == 0) {
        int all0 = 1;
        for (int i = 1; i < 4096; i += 2) {
            if (ei32[i] != 0) { all0 = 0; break; }
        }
        g_is64 = all0;
    }
}

// ---------------- small helpers ----------------
__global__ void zero_deg_kernel(int N) {
    int t = blockIdx.x * blockDim.x + threadIdx.x;
    if (t < N) g_deg[t] = 0.0f;
}

__global__ void deg_accum_kernel(const void* __restrict__ ei, int E) {
    int t = blockIdx.x * blockDim.x + threadIdx.x;
    if (t < E) atomicAdd(&g_deg[ld_idx(ei, (long long)E + t)], 1.0f);  // dst = row 1
}

__global__ void node_norm_kernel(int N) {
    int t = blockIdx.x * blockDim.x + threadIdx.x;
    if (t < N) {
        float d = g_deg[t] + 1.0f;
        float di = rsqrtf(d);
        g_deg[t]  = di;        // deg -> dinv
        g_self[t] = di * di;
    }
}

__global__ void edge_norm_kernel(const void* __restrict__ ei, int E) {
    int t = blockIdx.x * blockDim.x + threadIdx.x;
    if (t < E) {
        int s = ld_idx(ei, t);
        int d = ld_idx(ei, (long long)E + t);
        g_enorm[t] = g_deg[s] * g_deg[d];
    }
}

// ---------------- layer 1 matmul (32 -> 8), fused with agg init ----------------
// h -> bufA, agg(init = h*self) -> bufB
__global__ void mm1_fused_kernel(const float* __restrict__ x,
                                 const float* __restrict__ W, int N) {
    __shared__ float Ws[32 * 8];
    for (int i = threadIdx.x; i < 32 * 8; i += blockDim.x) Ws[i] = W[i];
    __syncthreads();
    int t = blockIdx.x * blockDim.x + threadIdx.x;
    int n = t >> 3, c = t & 7;
    if (n >= N) return;
    float acc = 0.0f;
    const float* xr = x + (size_t)n * 32;
#pragma unroll
    for (int k = 0; k < 32; k++) acc = fmaf(xr[k], Ws[k * 8 + c], acc);
    g_bufA[(size_t)n * 8 + c] = acc;
    g_bufB[(size_t)n * 8 + c] = acc * g_self[n];
}

// ---------------- node init:  out[n,:] = f(in[n,:]) * self[n]  (f = relu(.+b) optional)
__global__ void node_init_kernel(int inW, int outW,
                                 const float* __restrict__ bias,
                                 int total4, int D4, int applyBias) {
    int t = blockIdx.x * blockDim.x + threadIdx.x;
    if (t >= total4) return;
    const float* in  = selbuf(inW);
    float*       out = selbuf(outW);
    int n = t / D4, c4 = t % D4;
    float4 v = ((const float4*)in)[t];
    if (applyBias) {
        float4 b = ((const float4*)bias)[c4];
        v.x = fmaxf(v.x + b.x, 0.f);
        v.y = fmaxf(v.y + b.y, 0.f);
        v.z = fmaxf(v.z + b.z, 0.f);
        v.w = fmaxf(v.w + b.w, 0.f);
    }
    float sn = g_self[n];
    v.x *= sn; v.y *= sn; v.z *= sn; v.w *= sn;
    ((float4*)out)[t] = v;
}

// ---------------- edge scatter: out[dst,:] += f(in[src,:]) * enorm[e] ----------------
__global__ void edge_scatter_kernel(int inW, int outW,
                                    const float* __restrict__ bias,
                                    const void* __restrict__ ei, int E,
                                    int total4, int D4, int applyBias) {
    int t = blockIdx.x * blockDim.x + threadIdx.x;
    if (t >= total4) return;
    const float* in  = selbuf(inW);
    float*       out = selbuf(outW);
    int e = t / D4, c4 = t % D4;
    size_t s = (size_t)ld_idx(ei, e);
    size_t d = (size_t)ld_idx(ei, (long long)E + e);
    int D = D4 * 4;
    float4 v = *(const float4*)(in + s * D + c4 * 4);
    if (applyBias) {
        float4 b = ((const float4*)bias)[c4];
        v.x = fmaxf(v.x + b.x, 0.f);
        v.y = fmaxf(v.y + b.y, 0.f);
        v.z = fmaxf(v.z + b.z, 0.f);
        v.w = fmaxf(v.w + b.w, 0.f);
    }
    float w = g_enorm[e];
    float* o = out + d * D + c4 * 4;
    atomicAdd(o + 0, v.x * w);
    atomicAdd(o + 1, v.y * w);
    atomicAdd(o + 2, v.z * w);
    atomicAdd(o + 3, v.w * w);
}

// ---------------- small matmul (K,OUT small): C = relu(A@W + b) ----------------
template <int K, int OUT>
__global__ void mm_small_kernel(int inW, int outW,
                                const float* __restrict__ W,
                                const float* __restrict__ bias, int N) {
    __shared__ float Ws[K * OUT];
    __shared__ float bs[OUT];
    for (int i = threadIdx.x; i < K * OUT; i += blockDim.x) Ws[i] = W[i];
    for (int i = threadIdx.x; i < OUT; i += blockDim.x) bs[i] = bias[i];
    __syncthreads();
    const float* A = selbuf(inW);
    float*       C = selbuf(outW);
    int t = blockIdx.x * blockDim.x + threadIdx.x;
    int n = t / OUT, c = t % OUT;
    if (n >= N) return;
    const float* ar = A + (size_t)n * K;
    float acc = 0.0f;
#pragma unroll
    for (int k = 0; k < K; k++) acc = fmaf(ar[k], Ws[k * OUT + c], acc);
    C[(size_t)n * OUT + c] = fmaxf(acc + bs[c], 0.0f);
}

// ---------------- big tiled SGEMM: C[N,OUT] = relu(A[N,K]@W[K,OUT] + b) ----------------
// BM=128, BN=128, BK=16, TM=TN=8, 256 threads. K % 16 == 0, OUT % 128 == 0.
__global__ __launch_bounds__(256, 2)
void sgemm_bias_relu_kernel(int inW, int outW,
                            const float* __restrict__ W,
                            const float* __restrict__ bias,
                            int N, int K, int OUT) {
    constexpr int BM = 128, BN = 128, BK = 16, TM = 8, TN = 8;
    __shared__ float As[BK][BM];      // transposed A tile
    __shared__ float Bs[BK][BN];

    const float* A = selbuf(inW);
    float*       C = selbuf(outW);

    const int block_row = blockIdx.x * BM;
    const int block_col = blockIdx.y * BN;
    const int tid  = threadIdx.x;
    const int tcol = tid % (BN / TN);     // 0..15
    const int trow = tid / (BN / TN);     // 0..15

    float acc[TM][TN] = {};

    const int aRow  = tid / (BK / 4);          // 0..63
    const int aCol4 = (tid % (BK / 4)) * 4;    // 0,4,8,12
    const int wRow  = tid / (BN / 4);          // 0..7
    const int wCol4 = (tid % (BN / 4)) * 4;    // 0..124

    for (int k0 = 0; k0 < K; k0 += BK) {
#pragma unroll
        for (int i = 0; i < BM; i += 64) {
            int r    = i + aRow;
            int grow = block_row + r;
            float4 v = make_float4(0.f, 0.f, 0.f, 0.f);
            if (grow < N) v = *(const float4*)&A[(size_t)grow * K + k0 + aCol4];
            As[aCol4 + 0][r] = v.x;
            As[aCol4 + 1][r] = v.y;
            As[aCol4 + 2][r] = v.z;
            As[aCol4 + 3][r] = v.w;
        }
#pragma unroll
        for (int i = 0; i < BK; i += 8) {
            int r = i + wRow;
            float4 v = *(const float4*)&W[(size_t)(k0 + r) * OUT + block_col + wCol4];
            *(float4*)&Bs[r][wCol4] = v;
        }
        __syncthreads();

#pragma unroll
        for (int k = 0; k < BK; k++) {
            float regM[TM], regN[TN];
#pragma unroll
            for (int i = 0; i < TM; i++) regM[i] = As[k][trow * TM + i];
#pragma unroll
            for (int j = 0; j < TN; j++) regN[j] = Bs[k][tcol * TN + j];
#pragma unroll
            for (int i = 0; i < TM; i++)
#pragma unroll
                for (int j = 0; j < TN; j++)
                    acc[i][j] = fmaf(regM[i], regN[j], acc[i][j]);
        }
        __syncthreads();
    }

#pragma unroll
    for (int i = 0; i < TM; i++) {
        int grow = block_row + trow * TM + i;
        if (grow >= N) continue;
#pragma unroll
        for (int j = 0; j < TN; j += 4) {
            int gcol = block_col + tcol * TN + j;
            float4 o;
            o.x = fmaxf(acc[i][j + 0] + bias[gcol + 0], 0.f);
            o.y = fmaxf(acc[i][j + 1] + bias[gcol + 1], 0.f);
            o.z = fmaxf(acc[i][j + 2] + bias[gcol + 2], 0.f);
            o.w = fmaxf(acc[i][j + 3] + bias[gcol + 3], 0.f);
            *(float4*)&C[(size_t)grow * OUT + gcol] = o;
        }
    }
}

// ---------------- mean pool over sorted batch ids ----------------
__device__ __forceinline__ int lower_bound_idx(const void* a, int n, int v) {
    int lo = 0, hi = n;
    while (lo < hi) {
        int m = (lo + hi) >> 1;
        if (ld_idx(a, m) < v) lo = m + 1; else hi = m;
    }
    return lo;
}

__global__ void pool_kernel(int inW,
                            const void* __restrict__ batch,
                            float* __restrict__ out, int N, int B) {
    const float* x = selbuf(inW);
    int b = blockIdx.x;
    __shared__ int s_lo, s_hi;
    if (threadIdx.x == 0) {
        s_lo = lower_bound_idx(batch, N, b);
        s_hi = lower_bound_idx(batch, N, b + 1);
    }
    __syncthreads();
    int lo = s_lo, hi = s_hi;
    float inv = 1.0f / fmaxf((float)(hi - lo), 1.0f);
    for (int c = threadIdx.x; c < 512; c += blockDim.x) {
        float s = 0.0f;
        for (int n = lo; n < hi; n++) s += x[(size_t)n * 512 + c];
        out[(size_t)b * 512 + c] = s * inv;
    }
}

// ---------------- launch ----------------
static inline unsigned gr(long long n, int b) { return (unsigned)((n + b - 1) / b); }

extern "C" void kernel_launch(void* const* d_in, const int* in_sizes, int n_in,
                              void* d_out, int out_size) {
    const float* x     = (const float*)d_in[0];
    const void*  ei    = d_in[1];
    const void*  batch = d_in[2];
    const float *W1 = (const float*)d_in[3],  *b1 = (const float*)d_in[4];
    const float *W2 = (const float*)d_in[5],  *b2 = (const float*)d_in[6];
    const float *W3 = (const float*)d_in[7],  *b3 = (const float*)d_in[8];
    const float *W4 = (const float*)d_in[9],  *b4 = (const float*)d_in[10];
    const float *W5 = (const float*)d_in[11], *b5 = (const float*)d_in[12];

    const int N = in_sizes[0] / 32;
    const int E = in_sizes[1] / 2;
    const int B = out_size / 512;

    const int TB = 256;
    const int A = 0, Bb = 1;   // buffer selectors

    // index dtype detection, then normalization coefficients
    detect_kernel<<<1, 32>>>((const int*)ei);
    zero_deg_kernel<<<gr(N, TB), TB>>>(N);
    deg_accum_kernel<<<gr(E, TB), TB>>>(ei, E);
    node_norm_kernel<<<gr(N, TB), TB>>>(N);
    edge_norm_kernel<<<gr(E, TB), TB>>>(ei, E);

    // Layer 1 (32 -> 8): matmul first (out < in), then aggregate on dim 8.
    mm1_fused_kernel<<<gr((long long)N * 8, TB), TB>>>(x, W1, N);
    edge_scatter_kernel<<<gr((long long)E * 2, TB), TB>>>(A, Bb, nullptr, ei, E, E * 2, 2, 0);
    // bufB = A_hat @ (x@W1)  (pre bias+relu)

    // Layer 2 (8 -> 16): aggregate first on dim 8 (apply relu(.+b1) on the fly).
    node_init_kernel<<<gr((long long)N * 2, TB), TB>>>(Bb, A, b1, N * 2, 2, 1);
    edge_scatter_kernel<<<gr((long long)E * 2, TB), TB>>>(Bb, A, b1, ei, E, E * 2, 2, 1);
    mm_small_kernel<8, 16><<<gr((long long)N * 16, TB), TB>>>(A, Bb, W2, b2, N);   // bufB = x2 [N,16]

    // Layer 3 (16 -> 64): aggregate on dim 16.
    node_init_kernel<<<gr((long long)N * 4, TB), TB>>>(Bb, A, nullptr, N * 4, 4, 0);
    edge_scatter_kernel<<<gr((long long)E * 4, TB), TB>>>(Bb, A, nullptr, ei, E, E * 4, 4, 0);
    mm_small_kernel<16, 64><<<gr((long long)N * 64, TB), TB>>>(A, Bb, W3, b3, N);  // bufB = x3 [N,64]

    // Layer 4 (64 -> 256): aggregate on dim 64.
    node_init_kernel<<<gr((long long)N * 16, TB), TB>>>(Bb, A, nullptr, N * 16, 16, 0);
    edge_scatter_kernel<<<gr((long long)E * 16, TB), TB>>>(Bb, A, nullptr, ei, E, E * 16, 16, 0);
    {
        dim3 grid(gr(N, 128), 256 / 128);
        sgemm_bias_relu_kernel<<<grid, 256>>>(A, Bb, W4, b4, N, 64, 256);          // bufB = x4 [N,256]
    }

    // Layer 5 (256 -> 512): aggregate on dim 256.
    node_init_kernel<<<gr((long long)N * 64, TB), TB>>>(Bb, A, nullptr, N * 64, 64, 0);
    edge_scatter_kernel<<<gr((long long)E * 64, TB), TB>>>(Bb, A, nullptr, ei, E, E * 64, 64, 0);
    {
        dim3 grid(gr(N, 128), 512 / 128);
        sgemm_bias_relu_kernel<<<grid, 256>>>(A, Bb, W5, b5, N, 256, 512);         // bufB = x5 [N,512]
    }

    // Global mean pool
    pool_kernel<<<B, 512>>>(Bb, batch, (float*)d_out, N, B);
}

// round 5
// speedup vs baseline: 1.3330x; 1.3330x over previous
#include <cuda_runtime.h>
#include <cuda_bf16.h>
#include <math.h>

// Problem constants (match reference_code)
#define NN 50000
#define EE 400000
#define BB 50

// ---------------- scratch (static device allocations: allowed) ----------------
__device__ __align__(16) float g_bufA[(size_t)NN * 512];
__device__ __align__(16) float g_bufB[(size_t)NN * 512];
__device__ __align__(16) float g_dinv[NN];    // deg^-1/2
__device__ __align__(16) float g_self[NN];    // 1/deg
__device__ __align__(16) float g_ew[EE];      // per-CSR-slot edge weight
__device__ int   g_degi[NN];                  // int degree (no self loop)
__device__ int   g_rowptr[NN + 1];            // CSR row pointers (by dst)
__device__ int   g_cursor[NN];                // fill cursors
__device__ int   g_esrc[EE];                  // CSR column (src node) per slot
__device__ int   g_is64;                      // index dtype flag

__device__ __forceinline__ float* selbuf(int w) { return (w == 0) ? g_bufA : g_bufB; }

// Index accessor: element i of an index array that is either int32 or int64.
__device__ __forceinline__ int ld_idx(const void* p, long long i) {
    if (g_is64) return (int)((const long long*)p)[i];
    return ((const int*)p)[i];
}

// ---------------- dtype detection ----------------
__global__ void detect_kernel(const int* __restrict__ ei32) {
    if (threadIdx.x == 0 && blockIdx.x == 0) {
        int all0 = 1;
        for (int i = 1; i < 4096; i += 2) {
            if (ei32[i] != 0) { all0 = 0; break; }
        }
        g_is64 = all0;
    }
}

// ---------------- CSR build ----------------
__global__ void zero_degi_kernel(int N) {
    int t = blockIdx.x * blockDim.x + threadIdx.x;
    if (t < N) g_degi[t] = 0;
}

__global__ void deg_accum_kernel(const void* __restrict__ ei, int E) {
    int t = blockIdx.x * blockDim.x + threadIdx.x;
    if (t < E) atomicAdd(&g_degi[ld_idx(ei, (long long)E + t)], 1);  // dst row
}

// Single-block chunked exclusive scan over degi -> rowptr/cursor; also dinv/self.
__global__ void scan_kernel(int N) {
    __shared__ int sh[1024];
    __shared__ int carry_s;
    int tid = threadIdx.x;
    if (tid == 0) carry_s = 0;
    __syncthreads();
    for (int base = 0; base < N; base += 1024) {
        int i = base + tid;
        int v = (i < N) ? g_degi[i] : 0;
        sh[tid] = v;
        __syncthreads();
#pragma unroll
        for (int off = 1; off < 1024; off <<= 1) {
            int add = (tid >= off) ? sh[tid - off] : 0;
            __syncthreads();
            sh[tid] += add;
            __syncthreads();
        }
        int incl = sh[tid];
        int excl = incl - v;
        int carry = carry_s;
        if (i < N) {
            g_rowptr[i] = carry + excl;
            g_cursor[i] = carry + excl;
            float d  = (float)v + 1.0f;
            float di = rsqrtf(d);
            g_dinv[i] = di;
            g_self[i] = di * di;
        }
        __syncthreads();
        if (tid == 1023) carry_s = carry + incl;
        __syncthreads();
    }
    if (tid == 0) g_rowptr[N] = carry_s;
}

__global__ void fill_kernel(const void* __restrict__ ei, int E) {
    int e = blockIdx.x * blockDim.x + threadIdx.x;
    if (e >= E) return;
    int s = ld_idx(ei, e);
    int d = ld_idx(ei, (long long)E + e);
    int p = atomicAdd(&g_cursor[d], 1);
    g_esrc[p] = s;
    g_ew[p]   = g_dinv[s] * g_dinv[d];
}

// ---------------- layer 1 matmul (32 -> 8) ----------------
__global__ void mm1_kernel(const float* __restrict__ x,
                           const float* __restrict__ W, int N) {
    __shared__ float Ws[32 * 8];
    for (int i = threadIdx.x; i < 32 * 8; i += blockDim.x) Ws[i] = W[i];
    __syncthreads();
    int t = blockIdx.x * blockDim.x + threadIdx.x;
    int n = t >> 3, c = t & 7;
    if (n >= N) return;
    float acc = 0.0f;
    const float* xr = x + (size_t)n * 32;
#pragma unroll
    for (int k = 0; k < 32; k++) acc = fmaf(xr[k], Ws[k * 8 + c], acc);
    g_bufA[(size_t)n * 8 + c] = acc;
}

// ---------------- CSR gather aggregation ----------------
// out[n,:] = self[n]*f(in[n,:]) + sum_{p in row n} ew[p]*f(in[esrc[p],:])
// f = relu(. + bias) when BIAS, identity otherwise. D4 threads per node (float4 cols).
template <int D4, int BIAS>
__global__ void gather_agg_kernel(int inW, int outW,
                                  const float* __restrict__ bias, int N) {
    int t = blockIdx.x * blockDim.x + threadIdx.x;
    int n = t / D4, c4 = t % D4;
    if (n >= N) return;
    const float4* in4  = (const float4*)selbuf(inW);
    float4*       out4 = (float4*)selbuf(outW);

    float4 b = make_float4(0.f, 0.f, 0.f, 0.f);
    if (BIAS) b = ((const float4*)bias)[c4];

    float4 acc = in4[(size_t)n * D4 + c4];
    if (BIAS) {
        acc.x = fmaxf(acc.x + b.x, 0.f);
        acc.y = fmaxf(acc.y + b.y, 0.f);
        acc.z = fmaxf(acc.z + b.z, 0.f);
        acc.w = fmaxf(acc.w + b.w, 0.f);
    }
    float sn = g_self[n];
    acc.x *= sn; acc.y *= sn; acc.z *= sn; acc.w *= sn;

    int p0 = g_rowptr[n], p1 = g_rowptr[n + 1];
    for (int p = p0; p < p1; p++) {
        int   s = g_esrc[p];
        float w = g_ew[p];
        float4 v = in4[(size_t)s * D4 + c4];
        if (BIAS) {
            v.x = fmaxf(v.x + b.x, 0.f);
            v.y = fmaxf(v.y + b.y, 0.f);
            v.z = fmaxf(v.z + b.z, 0.f);
            v.w = fmaxf(v.w + b.w, 0.f);
        }
        acc.x = fmaf(v.x, w, acc.x);
        acc.y = fmaf(v.y, w, acc.y);
        acc.z = fmaf(v.z, w, acc.z);
        acc.w = fmaf(v.w, w, acc.w);
    }
    out4[(size_t)n * D4 + c4] = acc;
}

// ---------------- small matmul (K,OUT small): C = relu(A@W + b) ----------------
template <int K, int OUT>
__global__ void mm_small_kernel(int inW, int outW,
                                const float* __restrict__ W,
                                const float* __restrict__ bias, int N) {
    __shared__ float Ws[K * OUT];
    __shared__ float bs[OUT];
    for (int i = threadIdx.x; i < K * OUT; i += blockDim.x) Ws[i] = W[i];
    for (int i = threadIdx.x; i < OUT; i += blockDim.x) bs[i] = bias[i];
    __syncthreads();
    const float* A = selbuf(inW);
    float*       C = selbuf(outW);
    int t = blockIdx.x * blockDim.x + threadIdx.x;
    int n = t / OUT, c = t % OUT;
    if (n >= N) return;
    const float* ar = A + (size_t)n * K;
    float acc = 0.0f;
#pragma unroll
    for (int k = 0; k < K; k++) acc = fmaf(ar[k], Ws[k * OUT + c], acc);
    C[(size_t)n * OUT + c] = fmaxf(acc + bs[c], 0.0f);
}

// ---------------- big tiled SGEMM, double-buffered ----------------
// C[N,OUT] = relu(A[N,K]@W[K,OUT] + b). BM=BN=128, BK=16, TM=TN=8, 256 thr.
__global__ __launch_bounds__(256, 2)
void sgemm_bias_relu_kernel(int inW, int outW,
                            const float* __restrict__ W,
                            const float* __restrict__ bias,
                            int N, int K, int OUT) {
    constexpr int BM = 128, BN = 128, BK = 16, TM = 8, TN = 8;
    __shared__ float As[2][BK][BM];
    __shared__ float Bs[2][BK][BN];

    const float* A = selbuf(inW);
    float*       C = selbuf(outW);

    const int block_row = blockIdx.x * BM;
    const int block_col = blockIdx.y * BN;
    const int tid  = threadIdx.x;
    const int tcol = tid % (BN / TN);
    const int trow = tid / (BN / TN);

    float acc[TM][TN] = {};

    const int aRow  = tid / (BK / 4);          // 0..63
    const int aCol4 = (tid % (BK / 4)) * 4;    // 0,4,8,12
    const int wRow  = tid / (BN / 4);          // 0..7
    const int wCol4 = (tid % (BN / 4)) * 4;    // 0..124

    auto load_tile = [&](int buf, int k0) {
#pragma unroll
        for (int i = 0; i < BM; i += 64) {
            int r    = i + aRow;
            int grow = block_row + r;
            float4 v = make_float4(0.f, 0.f, 0.f, 0.f);
            if (grow < N) v = *(const float4*)&A[(size_t)grow * K + k0 + aCol4];
            As[buf][aCol4 + 0][r] = v.x;
            As[buf][aCol4 + 1][r] = v.y;
            As[buf][aCol4 + 2][r] = v.z;
            As[buf][aCol4 + 3][r] = v.w;
        }
#pragma unroll
        for (int i = 0; i < BK; i += 8) {
            int r = i + wRow;
            float4 v = *(const float4*)&W[(size_t)(k0 + r) * OUT + block_col + wCol4];
            *(float4*)&Bs[buf][r][wCol4] = v;
        }
    };

    load_tile(0, 0);
    __syncthreads();

    const int ntiles = K / BK;
    for (int ti = 0; ti < ntiles; ti++) {
        int cur = ti & 1;
        if (ti + 1 < ntiles) load_tile(cur ^ 1, (ti + 1) * BK);
#pragma unroll
        for (int k = 0; k < BK; k++) {
            float regM[TM], regN[TN];
#pragma unroll
            for (int i = 0; i < TM; i++) regM[i] = As[cur][k][trow * TM + i];
#pragma unroll
            for (int j = 0; j < TN; j++) regN[j] = Bs[cur][k][tcol * TN + j];
#pragma unroll
            for (int i = 0; i < TM; i++)
#pragma unroll
                for (int j = 0; j < TN; j++)
                    acc[i][j] = fmaf(regM[i], regN[j], acc[i][j]);
        }
        __syncthreads();
    }

#pragma unroll
    for (int i = 0; i < TM; i++) {
        int grow = block_row + trow * TM + i;
        if (grow >= N) continue;
#pragma unroll
        for (int j = 0; j < TN; j += 4) {
            int gcol = block_col + tcol * TN + j;
            float4 o;
            o.x = fmaxf(acc[i][j + 0] + bias[gcol + 0], 0.f);
            o.y = fmaxf(acc[i][j + 1] + bias[gcol + 1], 0.f);
            o.z = fmaxf(acc[i][j + 2] + bias[gcol + 2], 0.f);
            o.w = fmaxf(acc[i][j + 3] + bias[gcol + 3], 0.f);
            *(float4*)&C[(size_t)grow * OUT + gcol] = o;
        }
    }
}

// ---------------- mean pool over sorted batch ids ----------------
__device__ __forceinline__ int lower_bound_idx(const void* a, int n, int v) {
    int lo = 0, hi = n;
    while (lo < hi) {
        int m = (lo + hi) >> 1;
        if (ld_idx(a, m) < v) lo = m + 1; else hi = m;
    }
    return lo;
}

__global__ void pool_kernel(int inW,
                            const void* __restrict__ batch,
                            float* __restrict__ out, int N, int B) {
    const float* x = selbuf(inW);
    int b = blockIdx.x;
    int cbase = blockIdx.y * 128;
    __shared__ int s_lo, s_hi;
    if (threadIdx.x == 0) {
        s_lo = lower_bound_idx(batch, N, b);
        s_hi = lower_bound_idx(batch, N, b + 1);
    }
    __syncthreads();
    int lo = s_lo, hi = s_hi;
    float inv = 1.0f / fmaxf((float)(hi - lo), 1.0f);
    int c = cbase + threadIdx.x;
    float s = 0.0f;
    for (int n = lo; n < hi; n++) s += x[(size_t)n * 512 + c];
    out[(size_t)b * 512 + c] = s * inv;
}

// ---------------- launch ----------------
static inline unsigned gr(long long n, int b) { return (unsigned)((n + b - 1) / b); }

extern "C" void kernel_launch(void* const* d_in, const int* in_sizes, int n_in,
                              void* d_out, int out_size) {
    const float* x     = (const float*)d_in[0];
    const void*  ei    = d_in[1];
    const void*  batch = d_in[2];
    const float *W1 = (const float*)d_in[3],  *b1 = (const float*)d_in[4];
    const float *W2 = (const float*)d_in[5],  *b2 = (const float*)d_in[6];
    const float *W3 = (const float*)d_in[7],  *b3 = (const float*)d_in[8];
    const float *W4 = (const float*)d_in[9],  *b4 = (const float*)d_in[10];
    const float *W5 = (const float*)d_in[11], *b5 = (const float*)d_in[12];

    const int N = in_sizes[0] / 32;
    const int E = in_sizes[1] / 2;
    const int B = out_size / 512;

    const int TB = 256;
    const int A = 0, Bb = 1;   // buffer selectors

    // index dtype detection + CSR build + norms
    detect_kernel<<<1, 32>>>((const int*)ei);
    zero_degi_kernel<<<gr(N, TB), TB>>>(N);
    deg_accum_kernel<<<gr(E, TB), TB>>>(ei, E);
    scan_kernel<<<1, 1024>>>(N);
    fill_kernel<<<gr(E, TB), TB>>>(ei, E);

    // Layer 1 (32 -> 8): matmul into bufA, then CSR-gather aggregate (dim 8).
    mm1_kernel<<<gr((long long)N * 8, TB), TB>>>(x, W1, N);
    gather_agg_kernel<2, 0><<<gr((long long)N * 2, TB), TB>>>(A, Bb, nullptr, N);
    // bufB = A_hat @ (x@W1)   (pre bias+relu)

    // Layer 2 (8 -> 16): aggregate relu(bufB + b1) on dim 8, then matmul.
    gather_agg_kernel<2, 1><<<gr((long long)N * 2, TB), TB>>>(Bb, A, b1, N);
    mm_small_kernel<8, 16><<<gr((long long)N * 16, TB), TB>>>(A, Bb, W2, b2, N);   // bufB = x2 [N,16]

    // Layer 3 (16 -> 64): aggregate on dim 16.
    gather_agg_kernel<4, 0><<<gr((long long)N * 4, TB), TB>>>(Bb, A, nullptr, N);
    mm_small_kernel<16, 64><<<gr((long long)N * 64, TB), TB>>>(A, Bb, W3, b3, N);  // bufB = x3 [N,64]

    // Layer 4 (64 -> 256): aggregate on dim 64.
    gather_agg_kernel<16, 0><<<gr((long long)N * 16, TB), TB>>>(Bb, A, nullptr, N);
    {
        dim3 grid(gr(N, 128), 256 / 128);
        sgemm_bias_relu_kernel<<<grid, 256>>>(A, Bb, W4, b4, N, 64, 256);          // bufB = x4 [N,256]
    }

    // Layer 5 (256 -> 512): aggregate on dim 256.
    gather_agg_kernel<64, 0><<<gr((long long)N * 64, TB), TB>>>(Bb, A, nullptr, N);
    {
        dim3 grid(gr(N, 128), 512 / 128);
        sgemm_bias_relu_kernel<<<grid, 256>>>(A, Bb, W5, b5, N, 256, 512);         // bufB = x5 [N,512]
    }

    // Global mean pool
    dim3 pgrid(B, 4);
    pool_kernel<<<pgrid, 128>>>(Bb, batch, (float*)d_out, N, B);
}